// round 1
// baseline (speedup 1.0000x reference)
#include <cuda_runtime.h>

#define NQ    12
#define DIM   4096          // 2^12 amplitudes
#define NT    256           // threads per CTA
#define OCT   512           // 8-amplitude groups per fused-3 pass

// Frame tables. Phase 0: identity frame. Phase 1: after one CNOT chain (C).
// Phase 2: after two chains (C^2). MASK[ph][q] = F^{-1} e_q (partner-flip mask),
// ROWS[ph][q] = row q of F (logical bit value = parity(ROW & index)).
static __device__ constexpr int MASKS[3][12] = {
  {0x800,0x400,0x200,0x100,0x080,0x040,0x020,0x010,0x008,0x004,0x002,0x001},
  {0xC00,0x600,0x300,0x180,0x0C0,0x060,0x030,0x018,0x00C,0x006,0x003,0x001},
  {0xA00,0x500,0x280,0x140,0x0A0,0x050,0x028,0x014,0x00A,0x005,0x002,0x001}};
static __device__ constexpr int ROWS[3][12] = {
  {0x800,0x400,0x200,0x100,0x080,0x040,0x020,0x010,0x008,0x004,0x002,0x001},
  {0x800,0xC00,0xE00,0xF00,0xF80,0xFC0,0xFE0,0xFF0,0xFF8,0xFFC,0xFFE,0xFFF},
  {0x800,0x400,0xA00,0x500,0xA80,0x540,0xAA0,0x550,0xAA8,0x554,0xAAA,0x555}};

// Linear shared-memory swizzle (bank-conflict avoidance); commutes with XOR masks.
__device__ __forceinline__ int SW(int i) { return i ^ (i >> 3); }

// Generic fused 2x2 gate: n0 = a*w0 + b*w1 ; n1 = ph * (-b*w0 + a*w1)
// g = (a, b, ph.re, ph.im). Covers H*Z^x (a=b=r, ph=-e^{i pi x}) and
// Y^ty*Z^tz (a=cos, b=-sin, ph=e^{i pi tz}).
__device__ __forceinline__ void gate_pair(float2& w0, float2& w1, float4 g) {
    float n0x =  g.x * w0.x + g.y * w1.x;
    float n0y =  g.x * w0.y + g.y * w1.y;
    float tx  = -g.y * w0.x + g.x * w1.x;
    float ty  = -g.y * w0.y + g.x * w1.y;
    float n1x =  g.z * tx - g.w * ty;
    float n1y =  g.z * ty + g.w * tx;
    w0 = make_float2(n0x, n0y);
    w1 = make_float2(n1x, n1y);
}

// One sweep applying 3 single-qubit gates (qubits Q0, Q0+1, Q0+2) in frame PH.
// Pivot bits of the three masks are positions {11-Q0, 10-Q0, 9-Q0} (contiguous,
// upper-triangular -> valid coset transversal).
template<int PH, int Q0>
__device__ __forceinline__ void pass3(float2* s, const float4* g, int tid) {
    constexpr int mA = MASKS[PH][Q0], mB = MASKS[PH][Q0+1], mC = MASKS[PH][Q0+2];
    constexpr int rA = ROWS[PH][Q0],  rB = ROWS[PH][Q0+1],  rC = ROWS[PH][Q0+2];
    constexpr int sh = 9 - Q0;
    constexpr int smA = mA ^ (mA >> 3), smB = mB ^ (mB >> 3), smC = mC ^ (mC >> 3);
    const float4 gA = g[Q0], gB = g[Q0+1], gC = g[Q0+2];
    #pragma unroll
    for (int p = tid; p < OCT; p += NT) {
        int low  = p & ((1 << sh) - 1);
        int base = ((p >> sh) << (sh + 3)) | low;   // pivot bits zeroed
        int b000 = base;
        if (__popc(base & rA) & 1) b000 ^= mA;      // normalize roles so that
        if (__popc(base & rB) & 1) b000 ^= mB;      // w[x][y][z] holds logical
        if (__popc(base & rC) & 1) b000 ^= mC;      // bit values (x,y,z)
        int p000 = SW(b000);
        float2 w[2][2][2];
        #pragma unroll
        for (int x = 0; x < 2; x++)
        #pragma unroll
        for (int y = 0; y < 2; y++)
        #pragma unroll
        for (int z = 0; z < 2; z++)
            w[x][y][z] = s[p000 ^ (x ? smA : 0) ^ (y ? smB : 0) ^ (z ? smC : 0)];
        // gate A along x, gate B along y, gate C along z
        #pragma unroll
        for (int y = 0; y < 2; y++)
        #pragma unroll
        for (int z = 0; z < 2; z++) gate_pair(w[0][y][z], w[1][y][z], gA);
        #pragma unroll
        for (int x = 0; x < 2; x++)
        #pragma unroll
        for (int z = 0; z < 2; z++) gate_pair(w[x][0][z], w[x][1][z], gB);
        #pragma unroll
        for (int x = 0; x < 2; x++)
        #pragma unroll
        for (int y = 0; y < 2; y++) gate_pair(w[x][y][0], w[x][y][1], gC);
        #pragma unroll
        for (int x = 0; x < 2; x++)
        #pragma unroll
        for (int y = 0; y < 2; y++)
        #pragma unroll
        for (int z = 0; z < 2; z++)
            s[p000 ^ (x ? smA : 0) ^ (y ? smB : 0) ^ (z ? smC : 0)] = w[x][y][z];
    }
}

__global__ void __launch_bounds__(NT)
vqc_kernel(const float* __restrict__ inputs,
           const float* __restrict__ thetas,
           float* __restrict__ out) {
    __shared__ float2 s[DIM];
    __shared__ float4 genc[12];   // encoding gates (per-batch phases)
    __shared__ float4 gans[36];   // 3 layers x 12 qubits
    __shared__ float  red[12];

    const int tid = threadIdx.x;
    const int b   = blockIdx.x;

    // init |0...0>
    #pragma unroll
    for (int k = tid; k < DIM; k += NT) s[k] = make_float2(0.f, 0.f);
    if (tid == 0) s[0] = make_float2(1.f, 0.f);

    if (tid < 12) {
        float sn, cs;
        sincospif(inputs[b * 12 + tid], &sn, &cs);     // e^{i pi x}
        const float r = 0.70710678118654752f;
        genc[tid] = make_float4(r, r, -cs, -sn);       // ph = -e^{i pi x}
        red[tid] = 0.f;
    } else if (tid < 48) {
        int idx = tid - 12;                            // idx = l*12 + q
        float ty = thetas[2 * idx], tz = thetas[2 * idx + 1];
        float sy, cy, sz, cz;
        sincospif(0.5f * ty, &sy, &cy);                // cos/sin(pi*ty/2)
        sincospif(tz, &sz, &cz);                       // e^{i pi tz}
        gans[idx] = make_float4(cy, -sy, cz, sz);
    }
    __syncthreads();

    // Encoding: H + Z^x per qubit (frame 0)
    pass3<0, 0>(s, genc, tid); __syncthreads();
    pass3<0, 3>(s, genc, tid); __syncthreads();
    pass3<0, 6>(s, genc, tid); __syncthreads();
    pass3<0, 9>(s, genc, tid); __syncthreads();
    // Ansatz layer 0 (frame 0; its CNOT chain is absorbed into frame change)
    pass3<0, 0>(s, gans, tid); __syncthreads();
    pass3<0, 3>(s, gans, tid); __syncthreads();
    pass3<0, 6>(s, gans, tid); __syncthreads();
    pass3<0, 9>(s, gans, tid); __syncthreads();
    // Ansatz layer 1 (frame C)
    pass3<1, 0>(s, gans + 12, tid); __syncthreads();
    pass3<1, 3>(s, gans + 12, tid); __syncthreads();
    pass3<1, 6>(s, gans + 12, tid); __syncthreads();
    pass3<1, 9>(s, gans + 12, tid); __syncthreads();
    // Ansatz layer 2 (frame C^2, no trailing chain)
    pass3<2, 0>(s, gans + 24, tid); __syncthreads();
    pass3<2, 3>(s, gans + 24, tid); __syncthreads();
    pass3<2, 6>(s, gans + 24, tid); __syncthreads();
    pass3<2, 9>(s, gans + 24, tid); __syncthreads();

    // Readout: <Z_q> with signs from rows of C^2
    float acc[12];
    #pragma unroll
    for (int q = 0; q < 12; q++) acc[q] = 0.f;
    for (int k = tid; k < DIM; k += NT) {
        float2 a = s[SW(k)];
        float pr = a.x * a.x + a.y * a.y;
        #pragma unroll
        for (int q = 0; q < 12; q++)
            acc[q] += (__popc(k & ROWS[2][q]) & 1) ? -pr : pr;
    }
    #pragma unroll
    for (int q = 0; q < 12; q++) {
        #pragma unroll
        for (int o = 16; o; o >>= 1)
            acc[q] += __shfl_xor_sync(0xffffffffu, acc[q], o);
    }
    if ((tid & 31) == 0) {
        #pragma unroll
        for (int q = 0; q < 12; q++) atomicAdd(&red[q], acc[q]);
    }
    __syncthreads();
    if (tid < 12) out[b * 12 + tid] = red[tid];
}

extern "C" void kernel_launch(void* const* d_in, const int* in_sizes, int n_in,
                              void* d_out, int out_size) {
    const float* inputs = (const float*)d_in[0];   // [1024, 12] f32
    const float* thetas = (const float*)d_in[1];   // [72] f32
    float* out = (float*)d_out;                    // [1024, 12] f32
    vqc_kernel<<<1024, NT>>>(inputs, thetas, out);
}

// round 4
// speedup vs baseline: 2.0435x; 2.0435x over previous
#include <cuda_runtime.h>

#define NT 256
typedef unsigned long long u64;

// MASKS[ph][q] = F^{-1} e_q (partner-flip mask); ROWSF[ph][q] = row q of frame F.
constexpr int MASKS[3][12] = {
  {0x800,0x400,0x200,0x100,0x080,0x040,0x020,0x010,0x008,0x004,0x002,0x001},
  {0xC00,0x600,0x300,0x180,0x0C0,0x060,0x030,0x018,0x00C,0x006,0x003,0x001},
  {0xA00,0x500,0x280,0x140,0x0A0,0x050,0x028,0x014,0x00A,0x005,0x002,0x001}};
constexpr int ROWSF[3][12] = {
  {0x800,0x400,0x200,0x100,0x080,0x040,0x020,0x010,0x008,0x004,0x002,0x001},
  {0x800,0xC00,0xE00,0xF00,0xF80,0xFC0,0xFE0,0xFF0,0xFF8,0xFFC,0xFFE,0xFFF},
  {0x800,0x400,0xA00,0x500,0xA80,0x540,0xAA0,0x550,0xAA8,0x554,0xAAA,0x555}};

// Device-visible copy of the frame-C^2 rows for the readout sign computation.
__device__ __constant__ int ROWS2[12] =
  {0x800,0x400,0xA00,0x500,0xA80,0x540,0xAA0,0x550,0xAA8,0x554,0xAAA,0x555};

__host__ __device__ constexpr int SWc(int i) { return i ^ (i >> 3); }
__device__ __forceinline__ int SW(int i) { return i ^ (i >> 3); }

// ---- packed f32x2 helpers (re in low word, im in high word) ----
__device__ __forceinline__ u64 pk(float x, float y) {
    u64 r; asm("mov.b64 %0,{%1,%2};" : "=l"(r) : "f"(x), "f"(y)); return r;
}
__device__ __forceinline__ void upk(u64 v, float& x, float& y) {
    asm("mov.b64 {%0,%1},%2;" : "=f"(x), "=f"(y) : "l"(v));
}
__device__ __forceinline__ u64 swp(u64 v) { float x, y; upk(v, x, y); return pk(y, x); }
__device__ __forceinline__ u64 fma2(u64 a, u64 b, u64 c) {
    u64 r; asm("fma.rn.f32x2 %0,%1,%2,%3;" : "=l"(r) : "l"(a), "l"(b), "l"(c)); return r;
}
__device__ __forceinline__ u64 mul2(u64 a, u64 b) {
    u64 r; asm("mul.rn.f32x2 %0,%1,%2;" : "=l"(r) : "l"(a), "l"(b)); return r;
}

__device__ __forceinline__ float2 cmul(float2 a, float2 b) {
    return make_float2(fmaf(a.x, b.x, -a.y * b.y), fmaf(a.x, b.y, a.y * b.x));
}
__device__ __forceinline__ float2 loF(float4 v) { return make_float2(v.x, v.y); }
__device__ __forceinline__ float2 hiF(float4 v) { return make_float2(v.z, v.w); }

// Gate (special form): n0 = a*w0 + b*w1 ; n1 = ph * (-b*w0 + a*w1)
struct GateP { u64 aa, bb, nb, px, py; };
__device__ __forceinline__ GateP mkgate(float4 g) {
    GateP G;
    G.aa = pk(g.x, g.x);  G.bb = pk(g.y, g.y);  G.nb = pk(-g.y, -g.y);
    G.px = pk(g.z, g.z);  G.py = pk(-g.w, g.w);
    return G;
}
__device__ __forceinline__ void gp(u64& w0, u64& w1, const GateP& G) {
    u64 n0 = fma2(G.aa, w0, mul2(G.bb, w1));
    u64 t  = fma2(G.nb, w0, mul2(G.aa, w1));
    w1 = fma2(G.py, swp(t), mul2(G.px, t));   // ph * t (complex)
    w0 = n0;
}

// One sweep applying 4 gates (qubits Q0..Q0+3) in frame PH. Each thread owns
// exactly one 16-amp coset. Returns normalized base index b000 (logical bits 0).
template<int PH, int Q0, bool WB>
__device__ __forceinline__ int pass4(u64* s, const float4* gt, int p, u64* w) {
    constexpr int mA = MASKS[PH][Q0+0], mB = MASKS[PH][Q0+1];
    constexpr int mC = MASKS[PH][Q0+2], mD = MASKS[PH][Q0+3];
    constexpr int rA = ROWSF[PH][Q0+0], rB = ROWSF[PH][Q0+1];
    constexpr int rC = ROWSF[PH][Q0+2], rD = ROWSF[PH][Q0+3];
    constexpr int sh = 8 - Q0;
    constexpr int sA = SWc(mA), sB = SWc(mB), sC = SWc(mC), sD = SWc(mD);

    int low  = p & ((1 << sh) - 1);
    int base = ((p >> sh) << (sh + 4)) | low;      // pivot bits zero
    int b000 = base;                                // normalize logical bits to 0
    if (__popc(base & rA) & 1) b000 ^= mA;
    if (__popc(base & rB) & 1) b000 ^= mB;
    if (__popc(base & rC) & 1) b000 ^= mC;
    if (__popc(base & rD) & 1) b000 ^= mD;
    const int a0 = SW(b000);

    #pragma unroll
    for (int i = 0; i < 16; i++) {
        int off = ((i & 8) ? sA : 0) ^ ((i & 4) ? sB : 0) ^ ((i & 2) ? sC : 0) ^ ((i & 1) ? sD : 0);
        w[i] = s[a0 ^ off];
    }
    {   GateP G = mkgate(gt[Q0 + 0]);
        #pragma unroll
        for (int i = 0; i < 8; i++) gp(w[i], w[i + 8], G); }
    {   GateP G = mkgate(gt[Q0 + 1]);
        #pragma unroll
        for (int i = 0; i < 16; i++) if (!(i & 4)) gp(w[i], w[i + 4], G); }
    {   GateP G = mkgate(gt[Q0 + 2]);
        #pragma unroll
        for (int i = 0; i < 16; i++) if (!(i & 2)) gp(w[i], w[i + 2], G); }
    {   GateP G = mkgate(gt[Q0 + 3]);
        #pragma unroll
        for (int i = 0; i < 16; i++) if (!(i & 1)) gp(w[i], w[i + 1], G); }
    if (WB) {
        #pragma unroll
        for (int i = 0; i < 16; i++) {
            int off = ((i & 8) ? sA : 0) ^ ((i & 4) ? sB : 0) ^ ((i & 2) ? sC : 0) ^ ((i & 1) ? sD : 0);
            s[a0 ^ off] = w[i];
        }
    }
    return b000;
}

__global__ void __launch_bounds__(NT)
vqc_kernel(const float* __restrict__ inputs,
           const float* __restrict__ thetas,
           float* __restrict__ out) {
    __shared__ float2 st[4096];
    __shared__ float4 vtab[12];   // column-0 of merged (enc + ansatz-L0) gate
    __shared__ float4 gtab[24];   // L1, L2 gate params (a, b, ph.x, ph.y)
    __shared__ float  red[12];
    u64* s = reinterpret_cast<u64*>(st);

    const int tid = threadIdx.x;
    const int b   = blockIdx.x;

    // ---- per-qubit coefficients ----
    if (tid < 12) {
        int q = tid;
        float x  = inputs[b * 12 + q];
        float ty = thetas[2 * q], tz = thetas[2 * q + 1];
        float sx, cx, sy, cy, sz, cz;
        sincospif(x, &sx, &cx);            // e^{i pi x}
        sincospif(0.5f * ty, &sy, &cy);    // Y^ty entries
        sincospif(tz, &sz, &cz);           // e^{i pi tz}
        const float r = 0.70710678118654752f;
        // v = Z^tz * Y^ty * Z^x * H * (1,0)^T
        float v0x = r * (cy - sy * cx), v0y = -r * sy * sx;
        float tx = sy + cy * cx, tw = cy * sx;
        float v1x = r * (cz * tx - sz * tw), v1y = r * (cz * tw + sz * tx);
        vtab[q] = make_float4(v0x, v0y, v1x, v1y);
        red[q] = 0.f;
    } else if (tid < 36) {
        int idx = tid - 12;                 // (layer-1)*12 + q
        int l = idx / 12 + 1, q = idx % 12;
        float ty = thetas[l * 24 + 2 * q], tz = thetas[l * 24 + 2 * q + 1];
        float sy, cy, sz, cz;
        sincospif(0.5f * ty, &sy, &cy);
        sincospif(tz, &sz, &cz);
        gtab[idx] = make_float4(cy, -sy, cz, sz);
    }
    __syncthreads();

    // ---- init: product state after merged (enc + L0) layer, frame 0 ----
    {
        float4 v0q = vtab[0];
        float2 f = ((tid >> 7) & 1) ? hiF(v0q) : loF(v0q);
        #pragma unroll
        for (int q = 1; q < 8; q++) {
            float4 v = vtab[q];
            f = cmul(f, ((tid >> (7 - q)) & 1) ? hiF(v) : loF(v));
        }
        float4 v8 = vtab[8], v9 = vtab[9], vA = vtab[10], vB = vtab[11];
        float2 t8[2], t9[4], tA[8];
        t8[0] = cmul(f, loF(v8));  t8[1] = cmul(f, hiF(v8));
        #pragma unroll
        for (int j = 0; j < 2; j++) { t9[2*j] = cmul(t8[j], loF(v9)); t9[2*j+1] = cmul(t8[j], hiF(v9)); }
        #pragma unroll
        for (int j = 0; j < 4; j++) { tA[2*j] = cmul(t9[j], loF(vA)); tA[2*j+1] = cmul(t9[j], hiF(vA)); }
        #pragma unroll
        for (int l = 0; l < 16; l++) {
            float2 amp = cmul(tA[l >> 1], (l & 1) ? hiF(vB) : loF(vB));
            st[SW((tid << 4) | l)] = amp;
        }
    }
    __syncthreads();

    // ---- ansatz layers 1 (frame C) and 2 (frame C^2) ----
    u64 w[16];
    pass4<1, 0, true>(s, gtab,      tid, w); __syncthreads();
    pass4<1, 4, true>(s, gtab,      tid, w); __syncthreads();
    pass4<1, 8, true>(s, gtab,      tid, w); __syncthreads();
    pass4<2, 0, true>(s, gtab + 12, tid, w); __syncthreads();
    pass4<2, 4, true>(s, gtab + 12, tid, w); __syncthreads();
    int b000 = pass4<2, 8, false>(s, gtab + 12, tid, w);   // fused with readout

    // ---- readout directly from registers ----
    // q=0..7: sign depends only on b000; q=8..11: single-axis WHT components.
    float S = 0.f, d3 = 0.f, d2 = 0.f, d1 = 0.f, d0 = 0.f;
    #pragma unroll
    for (int i = 0; i < 16; i++) {
        float x, y; upk(w[i], x, y);
        float pr = fmaf(x, x, y * y);
        S += pr;
        d3 = (i & 8) ? d3 - pr : d3 + pr;
        d2 = (i & 4) ? d2 - pr : d2 + pr;
        d1 = (i & 2) ? d1 - pr : d1 + pr;
        d0 = (i & 1) ? d0 - pr : d0 + pr;
    }
    float acc[12];
    #pragma unroll
    for (int q = 0; q < 12; q++) {
        float v = (q < 8) ? S : (q == 8) ? d3 : (q == 9) ? d2 : (q == 10) ? d1 : d0;
        acc[q] = (__popc(b000 & ROWS2[q]) & 1) ? -v : v;
    }
    #pragma unroll
    for (int q = 0; q < 12; q++) {
        #pragma unroll
        for (int o = 16; o; o >>= 1)
            acc[q] += __shfl_xor_sync(0xffffffffu, acc[q], o);
    }
    if ((tid & 31) == 0) {
        #pragma unroll
        for (int q = 0; q < 12; q++) atomicAdd(&red[q], acc[q]);
    }
    __syncthreads();
    if (tid < 12) out[b * 12 + tid] = red[tid];
}

extern "C" void kernel_launch(void* const* d_in, const int* in_sizes, int n_in,
                              void* d_out, int out_size) {
    const float* inputs = (const float*)d_in[0];   // [1024, 12] f32
    const float* thetas = (const float*)d_in[1];   // [72] f32
    float* out = (float*)d_out;                    // [1024, 12] f32
    vqc_kernel<<<1024, NT>>>(inputs, thetas, out);
}